// round 8
// baseline (speedup 1.0000x reference)
#include <cuda_runtime.h>
#include <cuda_bf16.h>
#include <cstdint>

// SConv2dAvg as HMMA GEMM, cross-chunk pipelined, double-buffered.
// D[o,n] = sum_k W[o,k] P[k,n]; per CTA n = 16 b x 16 px = 256 cols.
// K=576 in 18 chunks of 32 (k' = (r*3+s)*64 + c).
// 3-product double-bf16 split: Whi*Phi + Whi*Plo + Wlo*Phi.
// 8 warps, warp tile m64 x n32, conflict-free scalar-LDS fragments (80B rows).

#define Y_DIM   63
#define COUT    64
#define KTOT    576
#define THREADS 256

// smem bytes: B bufs p=0,1: hi at p*40960, lo at p*40960+20480 (256 rows x 80B)
//             A bufs at 81920 + p*10240 (128 rows x 80B)
#define BBUF  40960
#define BLO   20480
#define ABASE 81920
#define ABUF  10240
#define SMEM_TOTAL 102400

__device__ unsigned short g_Ahi[COUT * KTOT];
__device__ unsigned short g_Alo[COUT * KTOT];

__global__ void prep_A_kernel(const float* __restrict__ w) {
    int idx = blockIdx.x * 256 + threadIdx.x;
    if (idx >= COUT * KTOT) return;
    int o  = idx / KTOT;
    int kp = idx - o * KTOT;        // k' = rs*64 + c
    int rs = kp >> 6;
    int c  = kp & 63;
    float v = w[o * KTOT + c * 9 + rs];
    unsigned short hi;
    asm("cvt.rn.bf16.f32 %0, %1;" : "=h"(hi) : "f"(v));
    float rem = v - __uint_as_float(((unsigned)hi) << 16);
    unsigned short lo;
    asm("cvt.rn.bf16.f32 %0, %1;" : "=h"(lo) : "f"(rem));
    g_Ahi[idx] = hi;
    g_Alo[idx] = lo;
}

__device__ __forceinline__ uint32_t pack_bf16x2(float x, float y) {
    uint32_t r;
    asm("cvt.rn.satfinite.bf16x2.f32 %0, %2, %1;" : "=r"(r) : "f"(x), "f"(y));
    return r;
}

#define MMA(acc, a, b)                                                         \
    asm volatile("mma.sync.aligned.m16n8k16.row.col.f32.bf16.bf16.f32 "        \
        "{%0,%1,%2,%3}, {%4,%5,%6,%7}, {%8,%9}, {%0,%1,%2,%3};"                \
        : "+f"((acc)[0]), "+f"((acc)[1]), "+f"((acc)[2]), "+f"((acc)[3])       \
        : "r"((a)[0]), "r"((a)[1]), "r"((a)[2]), "r"((a)[3]),                  \
          "r"((b)[0]), "r"((b)[1]))

// one k16 step from buffers (Bp = hi base, Ap = A base), conflict-free scalar LDS
#define COMPUTE_KQ(kq) do {                                                    \
    uint32_t bh_[4][2], bl_[4][2];                                             \
    _Pragma("unroll") for (int nf = 0; nf < 4; nf++) {                         \
        const char* pb = Bp + (w * 32 + nf * 8 + fr) * 80 + (kq) * 32 + fq * 4;\
        bh_[nf][0] = *(const uint32_t*)pb;                                     \
        bh_[nf][1] = *(const uint32_t*)(pb + 16);                              \
        bl_[nf][0] = *(const uint32_t*)(pb + BLO);                             \
        bl_[nf][1] = *(const uint32_t*)(pb + BLO + 16);                        \
    }                                                                          \
    _Pragma("unroll") for (int mf = 0; mf < 4; mf++) {                         \
        const char* pa = Ap + (mf * 16 + fr) * 80 + (kq) * 32 + fq * 4;        \
        uint32_t ah_[4], al_[4];                                               \
        ah_[0] = *(const uint32_t*)pa;                                         \
        ah_[1] = *(const uint32_t*)(pa + 8 * 80);                              \
        ah_[2] = *(const uint32_t*)(pa + 16);                                  \
        ah_[3] = *(const uint32_t*)(pa + 8 * 80 + 16);                         \
        al_[0] = *(const uint32_t*)(pa + 64 * 80);                             \
        al_[1] = *(const uint32_t*)(pa + 64 * 80 + 8 * 80);                    \
        al_[2] = *(const uint32_t*)(pa + 64 * 80 + 16);                        \
        al_[3] = *(const uint32_t*)(pa + 64 * 80 + 8 * 80 + 16);               \
        _Pragma("unroll") for (int nf = 0; nf < 4; nf++) {                     \
            MMA(acc[mf][nf], ah_, bh_[nf]);                                    \
            MMA(acc[mf][nf], ah_, bl_[nf]);                                    \
            MMA(acc[mf][nf], al_, bh_[nf]);                                    \
        }                                                                      \
    }                                                                          \
} while (0)

// load 16 gather values for half hh of chunk with plane base ppn
#define LDG16(v, hh)                                                           \
    _Pragma("unroll") for (int j = 0; j < 16; j++)                             \
        (v)[j] = __ldg(ppn + ((coffn + (hh) * 16 + j) << 14));

// convert 16 floats -> bf16 hi/lo, store into B buffer BN, half hh
#define CVT_STS(v, hh) do {                                                    \
    uint32_t hp[8], lp[8];                                                     \
    _Pragma("unroll") for (int q = 0; q < 8; q++) {                            \
        float a0 = (v)[2 * q], a1 = (v)[2 * q + 1];                            \
        hp[q] = pack_bf16x2(a0, a1);                                           \
        float r0 = a0 - __uint_as_float(hp[q] << 16);                          \
        float r1 = a1 - __uint_as_float(hp[q] & 0xFFFF0000u);                  \
        lp[q] = pack_bf16x2(r0, r1);                                           \
    }                                                                          \
    char* d = BN + tid * 80 + (hh) * 32;                                       \
    *(uint4*)(d)            = make_uint4(hp[0], hp[1], hp[2], hp[3]);          \
    *(uint4*)(d + 16)       = make_uint4(hp[4], hp[5], hp[6], hp[7]);          \
    *(uint4*)(d + BLO)      = make_uint4(lp[0], lp[1], lp[2], lp[3]);          \
    *(uint4*)(d + BLO + 16) = make_uint4(lp[4], lp[5], lp[6], lp[7]);          \
} while (0)

// load chunk chn's A slab (128 rows x 64B) into regs aa[2]
#define LDA(chn)                                                               \
    _Pragma("unroll") for (int i = 0; i < 2; i++) {                            \
        int idx = tid + i * 256;                                               \
        int q = idx >> 7, m = idx & 127;                                       \
        aa[i] = *(const uint4*)((const char*)(m < 64 ? g_Ahi : g_Alo)          \
                                + (m & 63) * 1152 + (chn) * 64 + q * 16);      \
    }

#define STA()                                                                  \
    _Pragma("unroll") for (int i = 0; i < 2; i++) {                            \
        int idx = tid + i * 256;                                               \
        int q = idx >> 7, m = idx & 127;                                       \
        *(uint4*)(AN + m * 80 + q * 16) = aa[i];                               \
    }

__global__ __launch_bounds__(THREADS, 2) void sconv_hmma_kernel(
    const float* __restrict__ input,
    const float* __restrict__ bias,
    const int*   __restrict__ selh,
    const int*   __restrict__ selw,
    float*       __restrict__ out)
{
    extern __shared__ char smem[];

    const int tid  = threadIdx.x;
    const int lane = tid & 31;
    const int w    = tid >> 5;
    const int fq   = lane & 3;
    const int fr   = lane >> 2;

    const int y   = blockIdx.x >> 2;
    const int px0 = (blockIdx.x & 3) * 16;

    // gather mapping: thread owns B row tid = b*16 + pxl, 32 c-values per chunk
    const int b   = tid >> 4;
    const int pxl = tid & 15;
    const int pxc = min(px0 + pxl, Y_DIM - 1);
    const int sh  = selh[y * Y_DIM + pxc];
    const int sw  = selw[y * Y_DIM + pxc];
    const float* pbase = input + (b << 20) + (2 * y + sh) * 128 + 2 * pxc + sw;

    float acc[4][4][4];
#pragma unroll
    for (int i = 0; i < 4; i++)
#pragma unroll
        for (int j = 0; j < 4; j++)
#pragma unroll
            for (int q = 0; q < 4; q++) acc[i][j][q] = 0.f;

    // ---- prologue: stage chunk 0 into buffers 0 ----
    {
        const float* ppn = pbase;       // chunk 0: plane (0,0), c-half 0
        const int coffn = 0;
        char* BN = smem;                // B buf 0 hi
        char* AN = smem + ABASE;        // A buf 0
        float v[16];
        uint4 aa[2];
        LDA(0);
        LDG16(v, 0);
        CVT_STS(v, 0);
        LDG16(v, 1);
        CVT_STS(v, 1);
        STA();
    }
    __syncthreads();

    // ---- main loop: compute ch from buf ch&1, pipeline gather of ch+1 ----
    for (int ch = 0; ch < 18; ch++) {
        const int p = ch & 1;
        const char* Bp = smem + p * BBUF;
        const char* Ap = smem + ABASE + p * ABUF;
        char* BN = smem + (p ^ 1) * BBUF;
        char* AN = smem + ABASE + (p ^ 1) * ABUF;

        const bool more = (ch < 17);
        const int chn  = ch + 1;
        const int rsn  = chn >> 1;
        const float* ppn = pbase + (rsn / 3) * 128 + (rsn - (rsn / 3) * 3);
        const int coffn = (chn & 1) * 32;

        float v[16];
        uint4 aa[2];

        if (more) { LDG16(v, 0); LDA(chn); }
        COMPUTE_KQ(0);
        if (more) {
            CVT_STS(v, 0);
            LDG16(v, 1);
        }
        COMPUTE_KQ(1);
        if (more) {
            CVT_STS(v, 1);
            STA();
        }
        __syncthreads();
    }

    // ---- epilogue: scalar stores (odd output strides) ----
    const int npx   = min(16, Y_DIM - px0);
    const int ybase = y * Y_DIM + px0;

#pragma unroll
    for (int mf = 0; mf < 4; mf++) {
        const int o = mf * 16 + fr;
        const float bo0 = __ldg(bias + o);
        const float bo8 = __ldg(bias + o + 8);
#pragma unroll
        for (int nf = 0; nf < 4; nf++) {
            int n    = w * 32 + nf * 8 + 2 * fq;
            int bcol = n >> 4;
            int pp   = n & 15;
            long base0 = ((long)(bcol * COUT + o)) * (Y_DIM * Y_DIM) + ybase + pp;
            long base8 = base0 + 8L * (Y_DIM * Y_DIM);
            if (pp < npx) {
                out[base0] = acc[mf][nf][0] + bo0;
                out[base8] = acc[mf][nf][2] + bo8;
            }
            if (pp + 1 < npx) {
                out[base0 + 1] = acc[mf][nf][1] + bo0;
                out[base8 + 1] = acc[mf][nf][3] + bo8;
            }
        }
    }
}

extern "C" void kernel_launch(void* const* d_in, const int* in_sizes, int n_in,
                              void* d_out, int out_size)
{
    const float* input  = (const float*)d_in[0];
    const float* weight = (const float*)d_in[1];
    const float* bias   = (const float*)d_in[2];
    const int*   selh   = (const int*)d_in[3];
    const int*   selw   = (const int*)d_in[4];
    float*       out    = (float*)d_out;

    cudaFuncSetAttribute(sconv_hmma_kernel,
                         cudaFuncAttributeMaxDynamicSharedMemorySize, SMEM_TOTAL);

    prep_A_kernel<<<(COUT * KTOT + 255) / 256, 256>>>(weight);
    sconv_hmma_kernel<<<Y_DIM * 4, THREADS, SMEM_TOTAL>>>(input, bias, selh, selw, out);
}